// round 2
// baseline (speedup 1.0000x reference)
#include <cuda_runtime.h>
#include <cstdint>
#include <cstddef>

// Problem constants
#define BB 32
#define LL 512
#define HH 1024
#define HID 512
#define G4 2048   // 4*HID
#define TWOH 2048 // 2*H

// ---------------------------------------------------------------------------
// Scratch (static __device__ arrays: allocation-free per harness rules)
// ---------------------------------------------------------------------------
__device__ __align__(16) float d_S[(size_t)BB * LL * LL];        // 32 MB: scores/att
__device__ __align__(16) float d_newx[(size_t)BB * LL * TWOH];   // 128 MB: [att@x, x]
__device__ __align__(16) float d_Gf[(size_t)LL * BB * G4];       // 128 MB: gates fwd, [t][b][4H]
__device__ __align__(16) float d_Gb[(size_t)LL * BB * G4];       // 128 MB: gates bwd
__device__ __align__(16) float d_hbuf[2][2][HID * BB];           // h ping-pong, [dir][buf][u*32+b]
__device__ unsigned d_bar[2];                                    // per-direction barrier counters

// ---------------------------------------------------------------------------
// init: zero h buffers + barrier counters (must re-zero every graph replay)
// ---------------------------------------------------------------------------
__global__ void init_state() {
    int i = blockIdx.x * blockDim.x + threadIdx.x;
    if (i < 2 * 2 * HID * BB) ((float*)d_hbuf)[i] = 0.0f;
    if (i < 2) d_bar[i] = 0u;
}

// ---------------------------------------------------------------------------
// Generic fp32 GEMM, 64x64 tile, K-step 16, 256 threads, 4x4 per thread.
//   TB=1: C = A * B^T   (A: MxK row-major, B: NxK row-major)
//   TB=0: C = A * B     (B: KxN row-major)
//   PERMC: row r=(b*512+t) of C is written to C[(t*32+b)*ldc + col] (time-major gates)
//   BIAS:  adds bias1[col]+bias2[col]
// ---------------------------------------------------------------------------
template <int TB, int PERMC, int BIAS>
__global__ void __launch_bounds__(256) sgemm64(
    const float* __restrict__ A, const float* __restrict__ Bm, float* __restrict__ C,
    int K, int lda, int ldb, int ldc,
    size_t sA, size_t sB, size_t sC,
    const float* __restrict__ bias1, const float* __restrict__ bias2)
{
    __shared__ __align__(16) float As[16][68];
    __shared__ __align__(16) float Bs[16][68];

    const int tid = threadIdx.x;
    const int tx = tid & 15, ty = tid >> 4;
    const int col0 = blockIdx.x * 64;
    const int row0 = blockIdx.y * 64;
    A  += (size_t)blockIdx.z * sA;
    Bm += (size_t)blockIdx.z * sB;
    C  += (size_t)blockIdx.z * sC;

    float acc[4][4] = {};

    for (int k0 = 0; k0 < K; k0 += 16) {
        #pragma unroll
        for (int i = 0; i < 4; i++) {
            int idx = tid + i * 256;
            int kk = idx & 15, rr = idx >> 4;
            As[kk][rr] = A[(size_t)(row0 + rr) * lda + (k0 + kk)];
        }
        #pragma unroll
        for (int i = 0; i < 4; i++) {
            int idx = tid + i * 256;
            if (TB) {
                int kk = idx & 15, cc = idx >> 4;
                Bs[kk][cc] = Bm[(size_t)(col0 + cc) * ldb + (k0 + kk)];
            } else {
                int cc = idx & 63, kk = idx >> 6;
                Bs[kk][cc] = Bm[(size_t)(k0 + kk) * ldb + (col0 + cc)];
            }
        }
        __syncthreads();
        #pragma unroll
        for (int kk = 0; kk < 16; kk++) {
            float4 a = *(const float4*)&As[kk][ty * 4];
            float4 b = *(const float4*)&Bs[kk][tx * 4];
            acc[0][0] += a.x * b.x; acc[0][1] += a.x * b.y; acc[0][2] += a.x * b.z; acc[0][3] += a.x * b.w;
            acc[1][0] += a.y * b.x; acc[1][1] += a.y * b.y; acc[1][2] += a.y * b.z; acc[1][3] += a.y * b.w;
            acc[2][0] += a.z * b.x; acc[2][1] += a.z * b.y; acc[2][2] += a.z * b.z; acc[2][3] += a.z * b.w;
            acc[3][0] += a.w * b.x; acc[3][1] += a.w * b.y; acc[3][2] += a.w * b.z; acc[3][3] += a.w * b.w;
        }
        __syncthreads();
    }

    float bv[4] = {0.f, 0.f, 0.f, 0.f};
    if (BIAS) {
        #pragma unroll
        for (int j = 0; j < 4; j++)
            bv[j] = bias1[col0 + tx * 4 + j] + bias2[col0 + tx * 4 + j];
    }
    #pragma unroll
    for (int i = 0; i < 4; i++) {
        int r = row0 + ty * 4 + i;
        #pragma unroll
        for (int j = 0; j < 4; j++) {
            int c = col0 + tx * 4 + j;
            float v = acc[i][j] + bv[j];
            if (PERMC) {
                int t = r & 511, bb = r >> 9;
                C[((size_t)t * 32 + bb) * ldc + c] = v;
            } else {
                C[(size_t)r * ldc + c] = v;
            }
        }
    }
}

// ---------------------------------------------------------------------------
// Masked softmax over last axis (512), matching m*s - (1-m)*1e20 semantics.
// One block of 256 threads per (l, b) row.
// ---------------------------------------------------------------------------
__global__ void __launch_bounds__(256) softmax512(float* __restrict__ S,
                                                  const float* __restrict__ mask)
{
    const int l = blockIdx.x, b = blockIdx.y;
    float* row = S + ((size_t)b * LL + l) * LL;
    const float* m = mask + (size_t)b * LL;
    const int tid = threadIdx.x;

    float m0 = m[tid], m1 = m[tid + 256];
    float v0 = (m0 > 0.5f) ? row[tid]       : -1e20f;
    float v1 = (m1 > 0.5f) ? row[tid + 256] : -1e20f;

    __shared__ float red[8];
    float mx = fmaxf(v0, v1);
    #pragma unroll
    for (int o = 16; o > 0; o >>= 1) mx = fmaxf(mx, __shfl_xor_sync(0xffffffffu, mx, o));
    if ((tid & 31) == 0) red[tid >> 5] = mx;
    __syncthreads();
    float bm = red[0];
    #pragma unroll
    for (int i = 1; i < 8; i++) bm = fmaxf(bm, red[i]);

    float e0 = expf(v0 - bm);
    float e1 = expf(v1 - bm);
    float sum = e0 + e1;
    #pragma unroll
    for (int o = 16; o > 0; o >>= 1) sum += __shfl_xor_sync(0xffffffffu, sum, o);
    __syncthreads();
    if ((tid & 31) == 0) red[tid >> 5] = sum;
    __syncthreads();
    float bs = 0.f;
    #pragma unroll
    for (int i = 0; i < 8; i++) bs += red[i];

    float inv = 1.0f / bs;
    row[tid]       = e0 * inv;
    row[tid + 256] = e1 * inv;
}

// ---------------------------------------------------------------------------
// Copy x into the second half of new_x (float4-vectorized)
// ---------------------------------------------------------------------------
__global__ void concat_copy(const float* __restrict__ x, float* __restrict__ nx)
{
    size_t i = (size_t)blockIdx.x * 256 + threadIdx.x;  // float4 index
    if (i >= (size_t)BB * LL * (HH / 4)) return;
    float4 v = ((const float4*)x)[i];
    size_t bl = i >> 8;     // b*512 + l
    size_t d4 = i & 255;    // float4 index within headdim
    ((float4*)nx)[bl * (TWOH / 4) + (HH / 4) + d4] = v;
}

// ---------------------------------------------------------------------------
// Persistent bidirectional LSTM recurrence.
// 128 blocks x 128 threads, all co-resident (1 block/SM via 128KB dyn smem,
// __launch_bounds__(128,1), 128 <= 148 SMs). Blocks 0..63: forward;
// 64..127: backward. Each block owns 8 hidden units (all 4 gates, all 32
// batches); one per-direction grid barrier per step.
// ---------------------------------------------------------------------------
__device__ __forceinline__ float sigm(float x) { return 1.0f / (1.0f + expf(-x)); }

__global__ void __launch_bounds__(128, 1) lstm_rec(
    const float* __restrict__ Whf, const float* __restrict__ Whb,
    const int* __restrict__ x_len, float* __restrict__ out)
{
    extern __shared__ __align__(16) float sm[];
    float* sW = sm;             // [512][32]  W_hh rows for this block, wT[k][lr]
    float* sH = sm + 512 * 32;  // [512][32]  hT[k][b]
    __shared__ float gbuf[32][33];
    __shared__ float cbuf[8][32];
    __shared__ int s_len[32];

    const int tid = threadIdx.x;
    const int dir = blockIdx.x >> 6;
    const int u0 = (blockIdx.x & 63) * 8;
    const float* __restrict__ G = dir ? d_Gb : d_Gf;
    const float* __restrict__ W = dir ? Whb : Whf;

    if (tid < 32) s_len[tid] = x_len[tid];
    for (int i = tid; i < 256; i += 128) ((float*)cbuf)[i] = 0.0f;

    // Stage this block's 32 W_hh rows into smem once:
    // local row lr = gate*8 + ui  ->  global row r = gate*512 + u0 + ui
    for (int lr = 0; lr < 32; lr++) {
        int r = (lr >> 3) * 512 + u0 + (lr & 7);
        const float* wr = W + (size_t)r * 512;
        for (int k = tid; k < 512; k += 128) sW[k * 32 + lr] = wr[k];
    }
    __syncthreads();

    const int bg = tid & 15, rg = tid >> 4;
    const int b0 = bg * 2, lr0 = rg * 4;
    const int gate = lr0 >> 3;
    const int r0 = gate * 512 + u0 + (lr0 & 7);

    for (int s = 0; s < 512; s++) {
        const int t = dir ? (511 - s) : s;
        const int rb = s & 1, wb = rb ^ 1;
        const float* hg = &d_hbuf[dir][rb][0];

        // load full h^T (this dir) into smem, L1-bypassed
        {
            const float4* hg4 = (const float4*)hg;
            float4* sH4 = (float4*)sH;
            for (int idx = tid; idx < (512 * 32) / 4; idx += 128)
                sH4[idx] = __ldcg(&hg4[idx]);
        }
        __syncthreads();

        // acc init from precomputed input gates G[t][b][r]
        const float* gp = G + (size_t)t * 32 * 2048;
        float4 a0 = *(const float4*)(gp + (size_t)(b0)     * 2048 + r0);
        float4 a1 = *(const float4*)(gp + (size_t)(b0 + 1) * 2048 + r0);
        float acc00 = a0.x, acc10 = a0.y, acc20 = a0.z, acc30 = a0.w;
        float acc01 = a1.x, acc11 = a1.y, acc21 = a1.z, acc31 = a1.w;

        const float* pW = sW + lr0;
        const float* pH = sH + b0;
        #pragma unroll 8
        for (int k = 0; k < 512; k++) {
            float4 w = *(const float4*)(pW + k * 32);
            float2 h = *(const float2*)(pH + k * 32);
            acc00 += w.x * h.x; acc01 += w.x * h.y;
            acc10 += w.y * h.x; acc11 += w.y * h.y;
            acc20 += w.z * h.x; acc21 += w.z * h.y;
            acc30 += w.w * h.x; acc31 += w.w * h.y;
        }

        gbuf[lr0 + 0][b0] = acc00; gbuf[lr0 + 0][b0 + 1] = acc01;
        gbuf[lr0 + 1][b0] = acc10; gbuf[lr0 + 1][b0 + 1] = acc11;
        gbuf[lr0 + 2][b0] = acc20; gbuf[lr0 + 2][b0 + 1] = acc21;
        gbuf[lr0 + 3][b0] = acc30; gbuf[lr0 + 3][b0 + 1] = acc31;
        __syncthreads();

        // LSTM pointwise for this block's 8 units x 32 batches
        for (int e = tid; e < 256; e += 128) {
            int ul = e >> 5, b = e & 31;
            float gi = gbuf[ul][b];
            float gf = gbuf[8 + ul][b];
            float gg = gbuf[16 + ul][b];
            float go = gbuf[24 + ul][b];
            float c  = cbuf[ul][b];
            float nc = sigm(gf) * c + sigm(gi) * tanhf(gg);
            float nh = sigm(go) * tanhf(nc);
            bool valid = (t < s_len[b]);
            float hold = sH[(u0 + ul) * 32 + b];
            float hn = valid ? nh : hold;
            float cn = valid ? nc : c;
            cbuf[ul][b] = cn;
            __stcg(&d_hbuf[dir][wb][(u0 + ul) * 32 + b], hn);
            if (s == 511) out[(size_t)b * 1024 + dir * 512 + (u0 + ul)] = hn;
        }

        if (s == 511) break;

        // per-direction grid barrier (monotonic counter, 64 blocks/dir)
        __threadfence();
        __syncthreads();
        if (tid == 0) {
            atomicAdd(&d_bar[dir], 1u);
            const unsigned target = 64u * (unsigned)(s + 1);
            while (true) {
                unsigned v;
                asm volatile("ld.global.acquire.gpu.u32 %0, [%1];" : "=r"(v) : "l"(&d_bar[dir]));
                if (v >= target) break;
                __nanosleep(64);
            }
            __threadfence();
        }
        __syncthreads();
    }
}

// ---------------------------------------------------------------------------
// kernel_launch
// ---------------------------------------------------------------------------
extern "C" void kernel_launch(void* const* d_in, const int* in_sizes, int n_in,
                              void* d_out, int out_size)
{
    const float* x    = (const float*)d_in[0];
    const int*   xlen = (const int*)  d_in[1];
    const float* am   = (const float*)d_in[2];
    const float* Wif  = (const float*)d_in[3];
    const float* Whf  = (const float*)d_in[4];
    const float* bif  = (const float*)d_in[5];
    const float* bhf  = (const float*)d_in[6];
    const float* Wib  = (const float*)d_in[7];
    const float* Whb  = (const float*)d_in[8];
    const float* bib  = (const float*)d_in[9];
    const float* bhb  = (const float*)d_in[10];
    float* out = (float*)d_out;

    void *pS, *pNX, *pGf, *pGb;
    cudaGetSymbolAddress(&pS,  d_S);
    cudaGetSymbolAddress(&pNX, d_newx);
    cudaGetSymbolAddress(&pGf, d_Gf);
    cudaGetSymbolAddress(&pGb, d_Gb);
    float* S  = (float*)pS;
    float* NX = (float*)pNX;
    float* Gf = (float*)pGf;
    float* Gb = (float*)pGb;

    // Opt-in to 128KB dynamic smem for the persistent kernel (idempotent;
    // non-stream API, legal during graph capture).
    cudaFuncSetAttribute(lstm_rec, cudaFuncAttributeMaxDynamicSharedMemorySize,
                         2 * 512 * 32 * (int)sizeof(float));

    init_state<<<256, 256>>>();

    // scores: S[b] = x_b * x_b^T   (M=512, N=512, K=1024)
    {
        dim3 g(512 / 64, 512 / 64, BB);
        sgemm64<1, 0, 0><<<g, 256>>>(x, x, S, 1024, 1024, 1024, 512,
                                     (size_t)LL * HH, (size_t)LL * HH, (size_t)LL * LL,
                                     nullptr, nullptr);
    }

    softmax512<<<dim3(LL, BB), 256>>>(S, am);

    // att @ x -> new_x[:, :, 0:1024]   (M=512, N=1024, K=512)
    {
        dim3 g(1024 / 64, 512 / 64, BB);
        sgemm64<0, 0, 0><<<g, 256>>>(S, x, NX, 512, 512, 1024, 2048,
                                     (size_t)LL * LL, (size_t)LL * HH, (size_t)LL * TWOH,
                                     nullptr, nullptr);
    }

    // new_x[:, :, 1024:2048] = x
    concat_copy<<<(BB * LL * (HH / 4) + 255) / 256, 256>>>(x, NX);

    // Gate precompute: G_d[t][b][:] = new_x[b][t][:] @ W_ih_d^T + (b_ih+b_hh)
    // (M=16384, N=2048, K=2048), output permuted to time-major
    {
        dim3 g(2048 / 64, 16384 / 64, 1);
        sgemm64<1, 1, 1><<<g, 256>>>(NX, Wif, Gf, 2048, 2048, 2048, 2048,
                                     0, 0, 0, bif, bhf);
        sgemm64<1, 1, 1><<<g, 256>>>(NX, Wib, Gb, 2048, 2048, 2048, 2048,
                                     0, 0, 0, bib, bhb);
    }

    // Persistent bidirectional recurrence
    lstm_rec<<<128, 128, 2 * 512 * 32 * sizeof(float)>>>(Whf, Whb, xlen, out);
}

// round 5
// speedup vs baseline: 1.7769x; 1.7769x over previous
#include <cuda_runtime.h>
#include <cuda_bf16.h>
#include <cstdint>
#include <cstddef>

// Problem constants
#define BB 32
#define LL 512
#define HH 1024
#define HID 512
#define G4 2048   // 4*HID
#define TWOH 2048 // 2*H

// ---------------------------------------------------------------------------
// Scratch (static __device__ arrays: allocation-free per harness rules)
// ---------------------------------------------------------------------------
__device__ __align__(16) float d_S[(size_t)BB * LL * LL];        // 32 MB: scores/att
__device__ __align__(16) float d_newx[(size_t)BB * LL * TWOH];   // 128 MB: [att@x, x]
__device__ __align__(16) float d_Gf[(size_t)LL * BB * G4];       // 128 MB: gates fwd, [t][b][4H]
__device__ __align__(16) float d_Gb[(size_t)LL * BB * G4];       // 128 MB: gates bwd
__device__ __align__(16) float d_hbuf[2][2][HID * BB];           // h ping-pong
__device__ unsigned d_bar[2];                                    // barrier counters
// bf16 split operands for tensor-core gate GEMM
__device__ __align__(16) __nv_bfloat16 d_NXhi[(size_t)BB * LL * TWOH];
__device__ __align__(16) __nv_bfloat16 d_NXlo[(size_t)BB * LL * TWOH];
__device__ __align__(16) __nv_bfloat16 d_Whi[2][(size_t)G4 * TWOH];
__device__ __align__(16) __nv_bfloat16 d_Wlo[2][(size_t)G4 * TWOH];

// ---------------------------------------------------------------------------
// PTX helpers — base sm_100-safe only (cp.async / ldmatrix / mma.sync)
// ---------------------------------------------------------------------------
__device__ __forceinline__ uint32_t smem_u32(const void* p) {
    uint32_t a;
    asm("{ .reg .u64 t; cvta.to.shared.u64 t, %1; cvt.u32.u64 %0, t; }" : "=r"(a) : "l"(p));
    return a;
}
__device__ __forceinline__ void cp_async16(uint32_t dst, const void* src) {
    asm volatile("cp.async.cg.shared.global [%0], [%1], 16;" :: "r"(dst), "l"(src));
}
#define CP_COMMIT() asm volatile("cp.async.commit_group;" ::: "memory")
#define CP_WAIT1()  asm volatile("cp.async.wait_group 1;" ::: "memory")

__device__ __forceinline__ void ldm_x4(uint32_t* r, uint32_t a) {
    asm volatile("ldmatrix.sync.aligned.m8n8.x4.shared.b16 {%0,%1,%2,%3}, [%4];"
                 : "=r"(r[0]), "=r"(r[1]), "=r"(r[2]), "=r"(r[3]) : "r"(a));
}
__device__ __forceinline__ void ldm_x2(uint32_t* r, uint32_t a) {
    asm volatile("ldmatrix.sync.aligned.m8n8.x2.shared.b16 {%0,%1}, [%2];"
                 : "=r"(r[0]), "=r"(r[1]) : "r"(a));
}
__device__ __forceinline__ void mma_bf16(float* d, const uint32_t* a, const uint32_t* b) {
    asm volatile("mma.sync.aligned.m16n8k16.row.col.f32.bf16.bf16.f32 "
                 "{%0,%1,%2,%3}, {%4,%5,%6,%7}, {%8,%9}, {%0,%1,%2,%3};"
                 : "+f"(d[0]), "+f"(d[1]), "+f"(d[2]), "+f"(d[3])
                 : "r"(a[0]), "r"(a[1]), "r"(a[2]), "r"(a[3]), "r"(b[0]), "r"(b[1]));
}

#define SWZ128(off) ((off) ^ (((off) >> 3) & 0x70))

// ---------------------------------------------------------------------------
// init: zero h buffers + barrier counters
// ---------------------------------------------------------------------------
__global__ void init_state() {
    int i = blockIdx.x * blockDim.x + threadIdx.x;
    if (i < 2 * 2 * HID * BB) ((float*)d_hbuf)[i] = 0.0f;
    if (i < 2) d_bar[i] = 0u;
}

// ---------------------------------------------------------------------------
// bf16 2-way split: hi = bf16(x), lo = bf16(x - hi)
// ---------------------------------------------------------------------------
__global__ void __launch_bounds__(256) split_bf16(
    const float* __restrict__ src, __nv_bfloat16* __restrict__ hi,
    __nv_bfloat16* __restrict__ lo, size_t n4)
{
    size_t i = (size_t)blockIdx.x * 256 + threadIdx.x;
    if (i >= n4) return;
    float4 v = ((const float4*)src)[i];
    __nv_bfloat16 h0 = __float2bfloat16(v.x), h1 = __float2bfloat16(v.y);
    __nv_bfloat16 h2 = __float2bfloat16(v.z), h3 = __float2bfloat16(v.w);
    __nv_bfloat162 H0 = {h0, h1}, H1 = {h2, h3};
    __nv_bfloat162 L0 = {__float2bfloat16(v.x - __bfloat162float(h0)),
                         __float2bfloat16(v.y - __bfloat162float(h1))};
    __nv_bfloat162 L1 = {__float2bfloat16(v.z - __bfloat162float(h2)),
                         __float2bfloat16(v.w - __bfloat162float(h3))};
    ((__nv_bfloat162*)hi)[i * 2]     = H0;
    ((__nv_bfloat162*)hi)[i * 2 + 1] = H1;
    ((__nv_bfloat162*)lo)[i * 2]     = L0;
    ((__nv_bfloat162*)lo)[i * 2 + 1] = L1;
}

// ---------------------------------------------------------------------------
// mma.sync bf16-split GEMM for gate precompute:
//   C[m,n] = sum_k A[m,k]*B[n,k] over 3 passes (Ahi*Bhi + Ahi*Blo + Alo*Bhi)
// CTA tile 128x128, 8 warps (2x4), warp tile 64x32, K-chunks of 64 bf16,
// double-buffered smem fed by cp.async. Output time-major with bias.
// ---------------------------------------------------------------------------
#define GK 2048
#define KC 64
#define NCHUNK 96                // 32 chunks x 3 passes
#define TILE_BYTES (128 * 128)   // 128 rows x 128B (64 bf16)
#define GEMM_DSMEM (1024 + 4 * TILE_BYTES)

__global__ void __launch_bounds__(256) gemm_gates(
    const __nv_bfloat16* __restrict__ Ahi, const __nv_bfloat16* __restrict__ Alo,
    const __nv_bfloat16* __restrict__ Bhi, const __nv_bfloat16* __restrict__ Blo,
    float* __restrict__ C,
    const float* __restrict__ bias1, const float* __restrict__ bias2)
{
    extern __shared__ char dsm[];
    char* base = (char*)(((uintptr_t)dsm + 1023) & ~(uintptr_t)1023);
    const uint32_t sbase = smem_u32(base);

    const int tid = threadIdx.x;
    const int wid = tid >> 5, lane = tid & 31;
    const int warp_m = wid >> 2, warp_n = wid & 3;
    const int m0 = blockIdx.y * 128, n0 = blockIdx.x * 128;

    float acc[4][4][4] = {};

    auto issue_chunk = [&](int chunk) {
        const int buf = chunk & 1;
        const int p = chunk >> 5;            // pass 0,1,2
        const int kc = (chunk & 31) * KC;    // k offset in elems
        const __nv_bfloat16* As = (p < 2) ? Ahi : Alo;
        const __nv_bfloat16* Bs = (p == 1) ? Blo : Bhi;
        const uint32_t sa = sbase + buf * 2 * TILE_BYTES;
        const uint32_t sb = sa + TILE_BYTES;
        #pragma unroll
        for (int i = 0; i < 4; i++) {
            int u = tid + i * 256;           // 1024 16B units per operand
            int r = u >> 3, cu = u & 7;
            uint32_t sw = SWZ128((uint32_t)(r * 128 + cu * 16));
            cp_async16(sa + sw, As + (size_t)(m0 + r) * GK + kc + cu * 8);
            cp_async16(sb + sw, Bs + (size_t)(n0 + r) * GK + kc + cu * 8);
        }
    };

    issue_chunk(0);
    CP_COMMIT();

    for (int c = 0; c < NCHUNK; c++) {
        if (c + 1 < NCHUNK) issue_chunk(c + 1);
        CP_COMMIT();
        CP_WAIT1();          // chunk c landed (chunk c+1 may be in flight)
        __syncthreads();

        const uint32_t sa = sbase + (c & 1) * 2 * TILE_BYTES;
        const uint32_t sb = sa + TILE_BYTES;

        #pragma unroll
        for (int ks = 0; ks < 4; ks++) {
            const int kb = ks * 32;   // 16 elems = 32 bytes per k-step
            uint32_t afr[4][4], bfr[4][2];
            #pragma unroll
            for (int mt = 0; mt < 4; mt++) {
                int row = warp_m * 64 + mt * 16 + (lane & 15);
                uint32_t off = SWZ128((uint32_t)(row * 128 + kb + ((lane >> 4) * 16)));
                ldm_x4(afr[mt], sa + off);
            }
            #pragma unroll
            for (int nt = 0; nt < 4; nt++) {
                int row = warp_n * 32 + nt * 8 + (lane & 7);
                uint32_t off = SWZ128((uint32_t)(row * 128 + kb + (((lane >> 3) & 1) * 16)));
                ldm_x2(bfr[nt], sb + off);
            }
            #pragma unroll
            for (int mt = 0; mt < 4; mt++)
                #pragma unroll
                for (int nt = 0; nt < 4; nt++)
                    mma_bf16(acc[mt][nt], afr[mt], bfr[nt]);
        }
        __syncthreads();
    }

    // Epilogue: time-major store with bias. m = b*512 + t -> row (t*32+b).
    const int g = lane >> 2, tc = lane & 3;
    #pragma unroll
    for (int nt = 0; nt < 4; nt++) {
        int col = n0 + warp_n * 32 + nt * 8 + tc * 2;
        float b0v = bias1[col] + bias2[col];
        float b1v = bias1[col + 1] + bias2[col + 1];
        #pragma unroll
        for (int mt = 0; mt < 4; mt++) {
            #pragma unroll
            for (int half = 0; half < 2; half++) {
                int m = m0 + warp_m * 64 + mt * 16 + g + half * 8;
                int t = m & 511, b = m >> 9;
                float2 v = { acc[mt][nt][half * 2] + b0v,
                             acc[mt][nt][half * 2 + 1] + b1v };
                *(float2*)(C + ((size_t)t * 32 + b) * 2048 + col) = v;
            }
        }
    }
}

// ---------------------------------------------------------------------------
// Generic fp32 GEMM (attention only), 64x64 tile.
// ---------------------------------------------------------------------------
template <int TB>
__global__ void __launch_bounds__(256) sgemm64(
    const float* __restrict__ A, const float* __restrict__ Bm, float* __restrict__ C,
    int K, int lda, int ldb, int ldc,
    size_t sA, size_t sB, size_t sC)
{
    __shared__ __align__(16) float As[16][68];
    __shared__ __align__(16) float Bs2[16][68];

    const int tid = threadIdx.x;
    const int tx = tid & 15, ty = tid >> 4;
    const int col0 = blockIdx.x * 64;
    const int row0 = blockIdx.y * 64;
    A  += (size_t)blockIdx.z * sA;
    Bm += (size_t)blockIdx.z * sB;
    C  += (size_t)blockIdx.z * sC;

    float acc[4][4] = {};

    for (int k0 = 0; k0 < K; k0 += 16) {
        #pragma unroll
        for (int i = 0; i < 4; i++) {
            int idx = tid + i * 256;
            int kk = idx & 15, rr = idx >> 4;
            As[kk][rr] = A[(size_t)(row0 + rr) * lda + (k0 + kk)];
        }
        #pragma unroll
        for (int i = 0; i < 4; i++) {
            int idx = tid + i * 256;
            if (TB) {
                int kk = idx & 15, cc = idx >> 4;
                Bs2[kk][cc] = Bm[(size_t)(col0 + cc) * ldb + (k0 + kk)];
            } else {
                int cc = idx & 63, kk = idx >> 6;
                Bs2[kk][cc] = Bm[(size_t)(k0 + kk) * ldb + (col0 + cc)];
            }
        }
        __syncthreads();
        #pragma unroll
        for (int kk = 0; kk < 16; kk++) {
            float4 a = *(const float4*)&As[kk][ty * 4];
            float4 b = *(const float4*)&Bs2[kk][tx * 4];
            acc[0][0] += a.x * b.x; acc[0][1] += a.x * b.y; acc[0][2] += a.x * b.z; acc[0][3] += a.x * b.w;
            acc[1][0] += a.y * b.x; acc[1][1] += a.y * b.y; acc[1][2] += a.y * b.z; acc[1][3] += a.y * b.w;
            acc[2][0] += a.z * b.x; acc[2][1] += a.z * b.y; acc[2][2] += a.z * b.z; acc[2][3] += a.z * b.w;
            acc[3][0] += a.w * b.x; acc[3][1] += a.w * b.y; acc[3][2] += a.w * b.z; acc[3][3] += a.w * b.w;
        }
        __syncthreads();
    }

    #pragma unroll
    for (int i = 0; i < 4; i++) {
        int r = row0 + ty * 4 + i;
        #pragma unroll
        for (int j = 0; j < 4; j++) {
            C[(size_t)r * ldc + (col0 + tx * 4 + j)] = acc[i][j];
        }
    }
}

// ---------------------------------------------------------------------------
// Masked softmax over last axis (512)
// ---------------------------------------------------------------------------
__global__ void __launch_bounds__(256) softmax512(float* __restrict__ S,
                                                  const float* __restrict__ mask)
{
    const int l = blockIdx.x, b = blockIdx.y;
    float* row = S + ((size_t)b * LL + l) * LL;
    const float* m = mask + (size_t)b * LL;
    const int tid = threadIdx.x;

    float m0 = m[tid], m1 = m[tid + 256];
    float v0 = (m0 > 0.5f) ? row[tid]       : -1e20f;
    float v1 = (m1 > 0.5f) ? row[tid + 256] : -1e20f;

    __shared__ float red[8];
    float mx = fmaxf(v0, v1);
    #pragma unroll
    for (int o = 16; o > 0; o >>= 1) mx = fmaxf(mx, __shfl_xor_sync(0xffffffffu, mx, o));
    if ((tid & 31) == 0) red[tid >> 5] = mx;
    __syncthreads();
    float bm = red[0];
    #pragma unroll
    for (int i = 1; i < 8; i++) bm = fmaxf(bm, red[i]);

    float e0 = expf(v0 - bm);
    float e1 = expf(v1 - bm);
    float sum = e0 + e1;
    #pragma unroll
    for (int o = 16; o > 0; o >>= 1) sum += __shfl_xor_sync(0xffffffffu, sum, o);
    __syncthreads();
    if ((tid & 31) == 0) red[tid >> 5] = sum;
    __syncthreads();
    float bs = 0.f;
    #pragma unroll
    for (int i = 0; i < 8; i++) bs += red[i];

    float inv = 1.0f / bs;
    row[tid]       = e0 * inv;
    row[tid + 256] = e1 * inv;
}

// ---------------------------------------------------------------------------
// Copy x into the second half of new_x
// ---------------------------------------------------------------------------
__global__ void concat_copy(const float* __restrict__ x, float* __restrict__ nx)
{
    size_t i = (size_t)blockIdx.x * 256 + threadIdx.x;
    if (i >= (size_t)BB * LL * (HH / 4)) return;
    float4 v = ((const float4*)x)[i];
    size_t bl = i >> 8;
    size_t d4 = i & 255;
    ((float4*)nx)[bl * (TWOH / 4) + (HH / 4) + d4] = v;
}

// ---------------------------------------------------------------------------
// Persistent bidirectional LSTM recurrence. 128 blocks x 256 threads,
// 1 block/SM (128KB dyn smem). Split-K x2: half-block accumulates
// k in [0,256), other half [256,512); combined in smem, pointwise fused.
// ---------------------------------------------------------------------------
__device__ __forceinline__ float sigm(float x) { return 1.0f / (1.0f + expf(-x)); }

__global__ void __launch_bounds__(256, 1) lstm_rec(
    const float* __restrict__ Whf, const float* __restrict__ Whb,
    const int* __restrict__ x_len, float* __restrict__ out)
{
    extern __shared__ __align__(16) float sm[];
    float* sW = sm;             // [512][32]  W_hh rows, wT[k][lr]
    float* sH = sm + 512 * 32;  // [512][32]  hT[k][b]
    __shared__ float gbuf2[2][32][33];
    __shared__ float cbuf[8][32];
    __shared__ int s_len[32];

    const int tid = threadIdx.x;
    const int dir = blockIdx.x >> 6;
    const int u0 = (blockIdx.x & 63) * 8;
    const float* __restrict__ G = dir ? d_Gb : d_Gf;
    const float* __restrict__ W = dir ? Whb : Whf;

    if (tid < 32) s_len[tid] = x_len[tid];
    ((float*)cbuf)[tid] = 0.0f;   // exactly 256 elems

    // Stage 32 W_hh rows: local row lr = gate*8 + ui -> global gate*512+u0+ui
    for (int lr = 0; lr < 32; lr++) {
        int r = (lr >> 3) * 512 + u0 + (lr & 7);
        const float* wr = W + (size_t)r * 512;
        for (int k = tid; k < 512; k += 256) sW[k * 32 + lr] = wr[k];
    }
    __syncthreads();

    const int kh = tid >> 7;            // k-half 0/1
    const int q  = tid & 127;
    const int b0 = (q & 15) * 2;
    const int lr0 = (q >> 4) * 4;
    const int gate = lr0 >> 3;
    const int r0 = gate * 512 + u0 + (lr0 & 7);
    const int kbeg = kh * 256, kend = kbeg + 256;

    for (int s = 0; s < 512; s++) {
        const int t = dir ? (511 - s) : s;
        const int rb = s & 1, wb = rb ^ 1;
        const float* hg = &d_hbuf[dir][rb][0];

        // load full h^T into smem
        {
            const float4* hg4 = (const float4*)hg;
            float4* sH4 = (float4*)sH;
            for (int idx = tid; idx < (512 * 32) / 4; idx += 256)
                sH4[idx] = __ldcg(&hg4[idx]);
        }
        __syncthreads();

        float acc00, acc10, acc20, acc30, acc01, acc11, acc21, acc31;
        if (kh == 0) {
            const float* gp = G + (size_t)t * 32 * 2048;
            float4 a0 = *(const float4*)(gp + (size_t)(b0)     * 2048 + r0);
            float4 a1 = *(const float4*)(gp + (size_t)(b0 + 1) * 2048 + r0);
            acc00 = a0.x; acc10 = a0.y; acc20 = a0.z; acc30 = a0.w;
            acc01 = a1.x; acc11 = a1.y; acc21 = a1.z; acc31 = a1.w;
        } else {
            acc00 = acc10 = acc20 = acc30 = 0.f;
            acc01 = acc11 = acc21 = acc31 = 0.f;
        }

        const float* pW = sW + lr0;
        const float* pH = sH + b0;
        #pragma unroll 8
        for (int k = kbeg; k < kend; k++) {
            float4 w = *(const float4*)(pW + k * 32);
            float2 h = *(const float2*)(pH + k * 32);
            acc00 += w.x * h.x; acc01 += w.x * h.y;
            acc10 += w.y * h.x; acc11 += w.y * h.y;
            acc20 += w.z * h.x; acc21 += w.z * h.y;
            acc30 += w.w * h.x; acc31 += w.w * h.y;
        }

        gbuf2[kh][lr0 + 0][b0] = acc00; gbuf2[kh][lr0 + 0][b0 + 1] = acc01;
        gbuf2[kh][lr0 + 1][b0] = acc10; gbuf2[kh][lr0 + 1][b0 + 1] = acc11;
        gbuf2[kh][lr0 + 2][b0] = acc20; gbuf2[kh][lr0 + 2][b0 + 1] = acc21;
        gbuf2[kh][lr0 + 3][b0] = acc30; gbuf2[kh][lr0 + 3][b0 + 1] = acc31;
        __syncthreads();

        // pointwise: one (unit, batch) per thread
        {
            const int ul = tid >> 5, b = tid & 31;
            float gi = gbuf2[0][ul][b]      + gbuf2[1][ul][b];
            float gf = gbuf2[0][8 + ul][b]  + gbuf2[1][8 + ul][b];
            float gg = gbuf2[0][16 + ul][b] + gbuf2[1][16 + ul][b];
            float go = gbuf2[0][24 + ul][b] + gbuf2[1][24 + ul][b];
            float c  = cbuf[ul][b];
            float nc = sigm(gf) * c + sigm(gi) * tanhf(gg);
            float nh = sigm(go) * tanhf(nc);
            bool valid = (t < s_len[b]);
            float hold = sH[(u0 + ul) * 32 + b];
            float hn = valid ? nh : hold;
            float cn = valid ? nc : c;
            cbuf[ul][b] = cn;
            __stcg(&d_hbuf[dir][wb][(u0 + ul) * 32 + b], hn);
            if (s == 511) out[(size_t)b * 1024 + dir * 512 + (u0 + ul)] = hn;
        }

        if (s == 511) break;

        // per-direction grid barrier (monotonic counter, 64 blocks/dir)
        __threadfence();
        __syncthreads();
        if (tid == 0) {
            atomicAdd(&d_bar[dir], 1u);
            const unsigned target = 64u * (unsigned)(s + 1);
            while (true) {
                unsigned v;
                asm volatile("ld.global.acquire.gpu.u32 %0, [%1];" : "=r"(v) : "l"(&d_bar[dir]));
                if (v >= target) break;
                __nanosleep(64);
            }
            __threadfence();
        }
        __syncthreads();
    }
}

// ---------------------------------------------------------------------------
// kernel_launch
// ---------------------------------------------------------------------------
extern "C" void kernel_launch(void* const* d_in, const int* in_sizes, int n_in,
                              void* d_out, int out_size)
{
    const float* x    = (const float*)d_in[0];
    const int*   xlen = (const int*)  d_in[1];
    const float* am   = (const float*)d_in[2];
    const float* Wif  = (const float*)d_in[3];
    const float* Whf  = (const float*)d_in[4];
    const float* bif  = (const float*)d_in[5];
    const float* bhf  = (const float*)d_in[6];
    const float* Wib  = (const float*)d_in[7];
    const float* Whb  = (const float*)d_in[8];
    const float* bib  = (const float*)d_in[9];
    const float* bhb  = (const float*)d_in[10];
    float* out = (float*)d_out;

    void *pS, *pNX, *pGf, *pGb, *pNXhi, *pNXlo, *pWhi, *pWlo;
    cudaGetSymbolAddress(&pS,  d_S);
    cudaGetSymbolAddress(&pNX, d_newx);
    cudaGetSymbolAddress(&pGf, d_Gf);
    cudaGetSymbolAddress(&pGb, d_Gb);
    cudaGetSymbolAddress(&pNXhi, d_NXhi);
    cudaGetSymbolAddress(&pNXlo, d_NXlo);
    cudaGetSymbolAddress(&pWhi, d_Whi);
    cudaGetSymbolAddress(&pWlo, d_Wlo);
    float* S  = (float*)pS;
    float* NX = (float*)pNX;
    float* Gf = (float*)pGf;
    float* Gb = (float*)pGb;
    __nv_bfloat16* NXhi = (__nv_bfloat16*)pNXhi;
    __nv_bfloat16* NXlo = (__nv_bfloat16*)pNXlo;
    __nv_bfloat16* Whi0 = (__nv_bfloat16*)pWhi;
    __nv_bfloat16* Whi1 = Whi0 + (size_t)G4 * TWOH;
    __nv_bfloat16* Wlo0 = (__nv_bfloat16*)pWlo;
    __nv_bfloat16* Wlo1 = Wlo0 + (size_t)G4 * TWOH;

    cudaFuncSetAttribute(lstm_rec, cudaFuncAttributeMaxDynamicSharedMemorySize,
                         2 * 512 * 32 * (int)sizeof(float));
    cudaFuncSetAttribute(gemm_gates, cudaFuncAttributeMaxDynamicSharedMemorySize,
                         GEMM_DSMEM);

    init_state<<<256, 256>>>();

    // scores: S[b] = x_b * x_b^T
    {
        dim3 g(512 / 64, 512 / 64, BB);
        sgemm64<1><<<g, 256>>>(x, x, S, 1024, 1024, 1024, 512,
                               (size_t)LL * HH, (size_t)LL * HH, (size_t)LL * LL);
    }

    softmax512<<<dim3(LL, BB), 256>>>(S, am);

    // att @ x -> new_x[:, :, 0:1024]
    {
        dim3 g(1024 / 64, 512 / 64, BB);
        sgemm64<0><<<g, 256>>>(S, x, NX, 512, 512, 1024, 2048,
                               (size_t)LL * LL, (size_t)LL * HH, (size_t)LL * TWOH);
    }

    concat_copy<<<(BB * LL * (HH / 4) + 255) / 256, 256>>>(x, NX);

    // bf16 splits
    {
        size_t n4 = (size_t)BB * LL * TWOH / 4;
        split_bf16<<<(unsigned)((n4 + 255) / 256), 256>>>(NX, NXhi, NXlo, n4);
        size_t w4 = (size_t)G4 * TWOH / 4;
        split_bf16<<<(unsigned)((w4 + 255) / 256), 256>>>(Wif, Whi0, Wlo0, w4);
        split_bf16<<<(unsigned)((w4 + 255) / 256), 256>>>(Wib, Whi1, Wlo1, w4);
    }

    // Gate precompute on tensor cores (bf16 split x3 passes), time-major out
    {
        dim3 g(2048 / 128, 16384 / 128);
        gemm_gates<<<g, 256, GEMM_DSMEM>>>(NXhi, NXlo, Whi0, Wlo0, Gf, bif, bhf);
        gemm_gates<<<g, 256, GEMM_DSMEM>>>(NXhi, NXlo, Whi1, Wlo1, Gb, bib, bhb);
    }

    // Persistent bidirectional recurrence
    lstm_rec<<<128, 256, 2 * 512 * 32 * sizeof(float)>>>(Whf, Whb, xlen, out);
}

// round 6
// speedup vs baseline: 2.0608x; 1.1598x over previous
#include <cuda_runtime.h>
#include <cuda_bf16.h>
#include <cstdint>
#include <cstddef>

// Problem constants
#define BB 32
#define LL 512
#define HH 1024
#define HID 512
#define G4 2048   // 4*HID
#define TWOH 2048 // 2*H

// ---------------------------------------------------------------------------
// Scratch (static __device__ arrays: allocation-free per harness rules)
// ---------------------------------------------------------------------------
__device__ __align__(16) float d_S[(size_t)BB * LL * LL];        // scores/att fp32
__device__ __align__(16) float d_Gf[(size_t)LL * BB * G4];       // gates fwd [t][b][4H]
__device__ __align__(16) float d_Gb[(size_t)LL * BB * G4];       // gates bwd
__device__ __align__(16) float d_hbuf[2][2][HID * BB];           // h ping-pong
__device__ unsigned d_bar[2];                                    // barrier counters
// bf16 split operands
__device__ __align__(16) __nv_bfloat16 d_xhi[(size_t)BB * LL * HH];
__device__ __align__(16) __nv_bfloat16 d_xlo[(size_t)BB * LL * HH];
__device__ __align__(16) __nv_bfloat16 d_xThi[(size_t)BB * HH * LL];  // x^T per batch
__device__ __align__(16) __nv_bfloat16 d_xTlo[(size_t)BB * HH * LL];
__device__ __align__(16) __nv_bfloat16 d_Shi[(size_t)BB * LL * LL];
__device__ __align__(16) __nv_bfloat16 d_Slo[(size_t)BB * LL * LL];
__device__ __align__(16) __nv_bfloat16 d_NXhi[(size_t)BB * LL * TWOH];
__device__ __align__(16) __nv_bfloat16 d_NXlo[(size_t)BB * LL * TWOH];
__device__ __align__(16) __nv_bfloat16 d_Whi[2][(size_t)G4 * TWOH];
__device__ __align__(16) __nv_bfloat16 d_Wlo[2][(size_t)G4 * TWOH];

// ---------------------------------------------------------------------------
// PTX helpers — base sm_100-safe only (cp.async / ldmatrix / mma.sync)
// ---------------------------------------------------------------------------
__device__ __forceinline__ uint32_t smem_u32(const void* p) {
    uint32_t a;
    asm("{ .reg .u64 t; cvta.to.shared.u64 t, %1; cvt.u32.u64 %0, t; }" : "=r"(a) : "l"(p));
    return a;
}
__device__ __forceinline__ void cp_async16(uint32_t dst, const void* src) {
    asm volatile("cp.async.cg.shared.global [%0], [%1], 16;" :: "r"(dst), "l"(src));
}
#define CP_COMMIT() asm volatile("cp.async.commit_group;" ::: "memory")
#define CP_WAIT1()  asm volatile("cp.async.wait_group 1;" ::: "memory")

__device__ __forceinline__ void ldm_x4(uint32_t* r, uint32_t a) {
    asm volatile("ldmatrix.sync.aligned.m8n8.x4.shared.b16 {%0,%1,%2,%3}, [%4];"
                 : "=r"(r[0]), "=r"(r[1]), "=r"(r[2]), "=r"(r[3]) : "r"(a));
}
__device__ __forceinline__ void ldm_x2(uint32_t* r, uint32_t a) {
    asm volatile("ldmatrix.sync.aligned.m8n8.x2.shared.b16 {%0,%1}, [%2];"
                 : "=r"(r[0]), "=r"(r[1]) : "r"(a));
}
__device__ __forceinline__ void mma_bf16(float* d, const uint32_t* a, const uint32_t* b) {
    asm volatile("mma.sync.aligned.m16n8k16.row.col.f32.bf16.bf16.f32 "
                 "{%0,%1,%2,%3}, {%4,%5,%6,%7}, {%8,%9}, {%0,%1,%2,%3};"
                 : "+f"(d[0]), "+f"(d[1]), "+f"(d[2]), "+f"(d[3])
                 : "r"(a[0]), "r"(a[1]), "r"(a[2]), "r"(a[3]), "r"(b[0]), "r"(b[1]));
}

#define SWZ128(off) ((off) ^ (((off) >> 3) & 0x70))

// ---------------------------------------------------------------------------
// init: zero h buffers + barrier counters
// ---------------------------------------------------------------------------
__global__ void init_state() {
    int i = blockIdx.x * blockDim.x + threadIdx.x;
    if (i < 2 * 2 * HID * BB) ((float*)d_hbuf)[i] = 0.0f;
    if (i < 2) d_bar[i] = 0u;
}

// ---------------------------------------------------------------------------
// Splits: hi = bf16(x), lo = bf16(x - hi)
// ---------------------------------------------------------------------------
__device__ __forceinline__ void split4(float4 v, __nv_bfloat162& H0, __nv_bfloat162& H1,
                                       __nv_bfloat162& L0, __nv_bfloat162& L1) {
    __nv_bfloat16 h0 = __float2bfloat16(v.x), h1 = __float2bfloat16(v.y);
    __nv_bfloat16 h2 = __float2bfloat16(v.z), h3 = __float2bfloat16(v.w);
    H0 = {h0, h1}; H1 = {h2, h3};
    L0 = {__float2bfloat16(v.x - __bfloat162float(h0)),
          __float2bfloat16(v.y - __bfloat162float(h1))};
    L1 = {__float2bfloat16(v.z - __bfloat162float(h2)),
          __float2bfloat16(v.w - __bfloat162float(h3))};
}

__global__ void __launch_bounds__(256) split_bf16(
    const float* __restrict__ src, __nv_bfloat16* __restrict__ hi,
    __nv_bfloat16* __restrict__ lo, size_t n4)
{
    size_t i = (size_t)blockIdx.x * 256 + threadIdx.x;
    if (i >= n4) return;
    __nv_bfloat162 H0, H1, L0, L1;
    split4(((const float4*)src)[i], H0, H1, L0, L1);
    ((__nv_bfloat162*)hi)[i * 2]     = H0;
    ((__nv_bfloat162*)hi)[i * 2 + 1] = H1;
    ((__nv_bfloat162*)lo)[i * 2]     = L0;
    ((__nv_bfloat162*)lo)[i * 2 + 1] = L1;
}

// split x AND write it into the second half of NX (x part of concat)
__global__ void __launch_bounds__(256) split_x(
    const float* __restrict__ x,
    __nv_bfloat16* __restrict__ xhi, __nv_bfloat16* __restrict__ xlo,
    __nv_bfloat16* __restrict__ NXhi, __nv_bfloat16* __restrict__ NXlo)
{
    size_t i = (size_t)blockIdx.x * 256 + threadIdx.x;   // float4 index
    if (i >= (size_t)BB * LL * HH / 4) return;
    __nv_bfloat162 H0, H1, L0, L1;
    split4(((const float4*)x)[i], H0, H1, L0, L1);
    ((__nv_bfloat162*)xhi)[i * 2]     = H0;
    ((__nv_bfloat162*)xhi)[i * 2 + 1] = H1;
    ((__nv_bfloat162*)xlo)[i * 2]     = L0;
    ((__nv_bfloat162*)xlo)[i * 2 + 1] = L1;
    size_t bl = i >> 8, d4 = i & 255;                    // 256 float4 per row
    size_t o = bl * 1024 + 512 + d4 * 2;                 // bf162 units, row=1024 units
    ((__nv_bfloat162*)NXhi)[o]     = H0;
    ((__nv_bfloat162*)NXhi)[o + 1] = H1;
    ((__nv_bfloat162*)NXlo)[o]     = L0;
    ((__nv_bfloat162*)NXlo)[o + 1] = L1;
}

// transpose xhi/xlo [b][512][1024] -> xThi/xTlo [b][1024][512]
__global__ void transpose_x(
    const __nv_bfloat16* __restrict__ hi, const __nv_bfloat16* __restrict__ lo,
    __nv_bfloat16* __restrict__ Thi, __nv_bfloat16* __restrict__ Tlo)
{
    __shared__ __nv_bfloat16 th[32][33], tl[32][33];
    const int b = blockIdx.z;
    const int d0 = blockIdx.x * 32, l0 = blockIdx.y * 32;
    const int tx = threadIdx.x, ty = threadIdx.y;      // (32, 8)
    const size_t si = (size_t)b * LL * HH;
    #pragma unroll
    for (int i = 0; i < 4; i++) {
        int l = ty + i * 8;
        th[l][tx] = hi[si + (size_t)(l0 + l) * HH + d0 + tx];
        tl[l][tx] = lo[si + (size_t)(l0 + l) * HH + d0 + tx];
    }
    __syncthreads();
    const size_t so = (size_t)b * HH * LL;
    #pragma unroll
    for (int i = 0; i < 4; i++) {
        int d = ty + i * 8;
        Thi[so + (size_t)(d0 + d) * LL + l0 + tx] = th[tx][d];
        Tlo[so + (size_t)(d0 + d) * LL + l0 + tx] = tl[tx][d];
    }
}

// ---------------------------------------------------------------------------
// Unified bf16-split tensor GEMM: C = A*B^T via hi*hi + hi*lo + lo*hi,
// all three products fused per K-chunk (operands loaded once).
// CTA tile 128x128, 8 warps (2x4), warp tile 64x32, KC=64, 2-stage cp.async.
// EPI=0: fp32 C (batched, ldc/sC)
// EPI=1: split-bf16 into Chi/Clo at row=(z*512+m), rowlen 2048 (NX first half)
// EPI=2: time-major gates: m=b*512+t -> row t*32+b, +bias1+bias2
// ---------------------------------------------------------------------------
#define KC 64
#define TILEB 16384              // 128 rows x 128B
#define STAGEB (4 * TILEB)       // Ahi,Alo,Bhi,Blo
#define T3_DSMEM (1024 + 2 * STAGEB)

template <int EPI>
__global__ void __launch_bounds__(256) gemm_t3(
    const __nv_bfloat16* __restrict__ Ahi, const __nv_bfloat16* __restrict__ Alo,
    const __nv_bfloat16* __restrict__ Bhi, const __nv_bfloat16* __restrict__ Blo,
    int K, int lda, int ldb, size_t sA, size_t sB,
    float* __restrict__ Cf, int ldc, size_t sC,
    __nv_bfloat16* __restrict__ Chi, __nv_bfloat16* __restrict__ Clo,
    const float* __restrict__ bias1, const float* __restrict__ bias2)
{
    extern __shared__ char dsm[];
    char* basep = (char*)(((uintptr_t)dsm + 1023) & ~(uintptr_t)1023);
    const uint32_t sbase = smem_u32(basep);

    const int tid = threadIdx.x;
    const int wid = tid >> 5, lane = tid & 31;
    const int warp_m = wid >> 2, warp_n = wid & 3;
    const int m0 = blockIdx.y * 128, n0 = blockIdx.x * 128;
    const int z = blockIdx.z;
    Ahi += (size_t)z * sA; Alo += (size_t)z * sA;
    Bhi += (size_t)z * sB; Blo += (size_t)z * sB;

    float acc[4][4][4] = {};
    const int nchunk = K / KC;

    auto issue = [&](int chunk) {
        const uint32_t st = sbase + (chunk & 1) * STAGEB;
        const int kc = chunk * KC;
        #pragma unroll
        for (int i = 0; i < 4; i++) {
            int u = tid + i * 256;               // 1024 16B units per tile
            int r = u >> 3, cu = u & 7;
            uint32_t sw = SWZ128((uint32_t)(r * 128 + cu * 16));
            size_t ao = (size_t)(m0 + r) * lda + kc + cu * 8;
            size_t bo = (size_t)(n0 + r) * ldb + kc + cu * 8;
            cp_async16(st + sw,             Ahi + ao);
            cp_async16(st + TILEB + sw,     Alo + ao);
            cp_async16(st + 2 * TILEB + sw, Bhi + bo);
            cp_async16(st + 3 * TILEB + sw, Blo + bo);
        }
    };

    issue(0);
    CP_COMMIT();

    for (int c = 0; c < nchunk; c++) {
        if (c + 1 < nchunk) issue(c + 1);
        CP_COMMIT();
        CP_WAIT1();
        __syncthreads();
        const uint32_t st = sbase + (c & 1) * STAGEB;

        #pragma unroll
        for (int ks = 0; ks < 4; ks++) {
            const int kb = ks * 32;
            uint32_t ah[4][4], al[4][4], bh[4][2], bl2[4][2];
            #pragma unroll
            for (int mt = 0; mt < 4; mt++) {
                int row = warp_m * 64 + mt * 16 + (lane & 15);
                uint32_t off = SWZ128((uint32_t)(row * 128 + kb + ((lane >> 4) * 16)));
                ldm_x4(ah[mt], st + off);
                ldm_x4(al[mt], st + TILEB + off);
            }
            #pragma unroll
            for (int nt = 0; nt < 4; nt++) {
                int row = warp_n * 32 + nt * 8 + (lane & 7);
                uint32_t off = SWZ128((uint32_t)(row * 128 + kb + (((lane >> 3) & 1) * 16)));
                ldm_x2(bh[nt],  st + 2 * TILEB + off);
                ldm_x2(bl2[nt], st + 3 * TILEB + off);
            }
            #pragma unroll
            for (int mt = 0; mt < 4; mt++)
                #pragma unroll
                for (int nt = 0; nt < 4; nt++) {
                    mma_bf16(acc[mt][nt], ah[mt], bh[nt]);
                    mma_bf16(acc[mt][nt], ah[mt], bl2[nt]);
                    mma_bf16(acc[mt][nt], al[mt], bh[nt]);
                }
        }
        __syncthreads();
    }

    // Epilogue
    const int g = lane >> 2, tc = lane & 3;
    #pragma unroll
    for (int nt = 0; nt < 4; nt++) {
        int col = n0 + warp_n * 32 + nt * 8 + tc * 2;
        float b0v = 0.f, b1v = 0.f;
        if (EPI == 2) {
            b0v = bias1[col] + bias2[col];
            b1v = bias1[col + 1] + bias2[col + 1];
        }
        #pragma unroll
        for (int mt = 0; mt < 4; mt++) {
            #pragma unroll
            for (int half = 0; half < 2; half++) {
                int ml = warp_m * 64 + mt * 16 + g + half * 8;
                float v0 = acc[mt][nt][half * 2] + b0v;
                float v1 = acc[mt][nt][half * 2 + 1] + b1v;
                if (EPI == 0) {
                    *(float2*)(Cf + (size_t)z * sC + (size_t)(m0 + ml) * ldc + col)
                        = make_float2(v0, v1);
                } else if (EPI == 1) {
                    size_t row = (size_t)z * LL + m0 + ml;
                    __nv_bfloat16 h0 = __float2bfloat16(v0), h1 = __float2bfloat16(v1);
                    __nv_bfloat162 hv = {h0, h1};
                    __nv_bfloat162 lv = {__float2bfloat16(v0 - __bfloat162float(h0)),
                                         __float2bfloat16(v1 - __bfloat162float(h1))};
                    *(__nv_bfloat162*)(Chi + row * TWOH + col) = hv;
                    *(__nv_bfloat162*)(Clo + row * TWOH + col) = lv;
                } else {
                    int m = m0 + ml;
                    int t = m & 511, b = m >> 9;
                    *(float2*)(Cf + ((size_t)t * 32 + b) * 2048 + col)
                        = make_float2(v0, v1);
                }
            }
        }
    }
}

// ---------------------------------------------------------------------------
// Masked softmax over last axis (512)
// ---------------------------------------------------------------------------
__global__ void __launch_bounds__(256) softmax512(float* __restrict__ S,
                                                  const float* __restrict__ mask)
{
    const int l = blockIdx.x, b = blockIdx.y;
    float* row = S + ((size_t)b * LL + l) * LL;
    const float* m = mask + (size_t)b * LL;
    const int tid = threadIdx.x;

    float m0 = m[tid], m1 = m[tid + 256];
    float v0 = (m0 > 0.5f) ? row[tid]       : -1e20f;
    float v1 = (m1 > 0.5f) ? row[tid + 256] : -1e20f;

    __shared__ float red[8];
    float mx = fmaxf(v0, v1);
    #pragma unroll
    for (int o = 16; o > 0; o >>= 1) mx = fmaxf(mx, __shfl_xor_sync(0xffffffffu, mx, o));
    if ((tid & 31) == 0) red[tid >> 5] = mx;
    __syncthreads();
    float bm = red[0];
    #pragma unroll
    for (int i = 1; i < 8; i++) bm = fmaxf(bm, red[i]);

    float e0 = expf(v0 - bm);
    float e1 = expf(v1 - bm);
    float sum = e0 + e1;
    #pragma unroll
    for (int o = 16; o > 0; o >>= 1) sum += __shfl_xor_sync(0xffffffffu, sum, o);
    __syncthreads();
    if ((tid & 31) == 0) red[tid >> 5] = sum;
    __syncthreads();
    float bs = 0.f;
    #pragma unroll
    for (int i = 0; i < 8; i++) bs += red[i];

    float inv = 1.0f / bs;
    row[tid]       = e0 * inv;
    row[tid + 256] = e1 * inv;
}

// ---------------------------------------------------------------------------
// Persistent bidirectional LSTM recurrence (unchanged from passing round 5).
// ---------------------------------------------------------------------------
__device__ __forceinline__ float sigm(float x) { return 1.0f / (1.0f + expf(-x)); }

__global__ void __launch_bounds__(256, 1) lstm_rec(
    const float* __restrict__ Whf, const float* __restrict__ Whb,
    const int* __restrict__ x_len, float* __restrict__ out)
{
    extern __shared__ __align__(16) float sm[];
    float* sW = sm;             // [512][32]  W_hh rows, wT[k][lr]
    float* sH = sm + 512 * 32;  // [512][32]  hT[k][b]
    __shared__ float gbuf2[2][32][33];
    __shared__ float cbuf[8][32];
    __shared__ int s_len[32];

    const int tid = threadIdx.x;
    const int dir = blockIdx.x >> 6;
    const int u0 = (blockIdx.x & 63) * 8;
    const float* __restrict__ G = dir ? d_Gb : d_Gf;
    const float* __restrict__ W = dir ? Whb : Whf;

    if (tid < 32) s_len[tid] = x_len[tid];
    ((float*)cbuf)[tid] = 0.0f;

    for (int lr = 0; lr < 32; lr++) {
        int r = (lr >> 3) * 512 + u0 + (lr & 7);
        const float* wr = W + (size_t)r * 512;
        for (int k = tid; k < 512; k += 256) sW[k * 32 + lr] = wr[k];
    }
    __syncthreads();

    const int kh = tid >> 7;
    const int q  = tid & 127;
    const int b0 = (q & 15) * 2;
    const int lr0 = (q >> 4) * 4;
    const int gate = lr0 >> 3;
    const int r0 = gate * 512 + u0 + (lr0 & 7);
    const int kbeg = kh * 256, kend = kbeg + 256;

    for (int s = 0; s < 512; s++) {
        const int t = dir ? (511 - s) : s;
        const int rb = s & 1, wb = rb ^ 1;
        const float* hg = &d_hbuf[dir][rb][0];

        {
            const float4* hg4 = (const float4*)hg;
            float4* sH4 = (float4*)sH;
            for (int idx = tid; idx < (512 * 32) / 4; idx += 256)
                sH4[idx] = __ldcg(&hg4[idx]);
        }
        __syncthreads();

        float acc00, acc10, acc20, acc30, acc01, acc11, acc21, acc31;
        if (kh == 0) {
            const float* gp = G + (size_t)t * 32 * 2048;
            float4 a0 = *(const float4*)(gp + (size_t)(b0)     * 2048 + r0);
            float4 a1 = *(const float4*)(gp + (size_t)(b0 + 1) * 2048 + r0);
            acc00 = a0.x; acc10 = a0.y; acc20 = a0.z; acc30 = a0.w;
            acc01 = a1.x; acc11 = a1.y; acc21 = a1.z; acc31 = a1.w;
        } else {
            acc00 = acc10 = acc20 = acc30 = 0.f;
            acc01 = acc11 = acc21 = acc31 = 0.f;
        }

        const float* pW = sW + lr0;
        const float* pH = sH + b0;
        #pragma unroll 8
        for (int k = kbeg; k < kend; k++) {
            float4 w = *(const float4*)(pW + k * 32);
            float2 h = *(const float2*)(pH + k * 32);
            acc00 += w.x * h.x; acc01 += w.x * h.y;
            acc10 += w.y * h.x; acc11 += w.y * h.y;
            acc20 += w.z * h.x; acc21 += w.z * h.y;
            acc30 += w.w * h.x; acc31 += w.w * h.y;
        }

        gbuf2[kh][lr0 + 0][b0] = acc00; gbuf2[kh][lr0 + 0][b0 + 1] = acc01;
        gbuf2[kh][lr0 + 1][b0] = acc10; gbuf2[kh][lr0 + 1][b0 + 1] = acc11;
        gbuf2[kh][lr0 + 2][b0] = acc20; gbuf2[kh][lr0 + 2][b0 + 1] = acc21;
        gbuf2[kh][lr0 + 3][b0] = acc30; gbuf2[kh][lr0 + 3][b0 + 1] = acc31;
        __syncthreads();

        {
            const int ul = tid >> 5, b = tid & 31;
            if (tid < 256) {
                float gi = gbuf2[0][ul][b]      + gbuf2[1][ul][b];
                float gf = gbuf2[0][8 + ul][b]  + gbuf2[1][8 + ul][b];
                float gg = gbuf2[0][16 + ul][b] + gbuf2[1][16 + ul][b];
                float go = gbuf2[0][24 + ul][b] + gbuf2[1][24 + ul][b];
                float c  = cbuf[ul][b];
                float nc = sigm(gf) * c + sigm(gi) * tanhf(gg);
                float nh = sigm(go) * tanhf(nc);
                bool valid = (t < s_len[b]);
                float hold = sH[(u0 + ul) * 32 + b];
                float hn = valid ? nh : hold;
                float cn = valid ? nc : c;
                cbuf[ul][b] = cn;
                __stcg(&d_hbuf[dir][wb][(u0 + ul) * 32 + b], hn);
                if (s == 511) out[(size_t)b * 1024 + dir * 512 + (u0 + ul)] = hn;
            }
        }

        if (s == 511) break;

        __threadfence();
        __syncthreads();
        if (tid == 0) {
            atomicAdd(&d_bar[dir], 1u);
            const unsigned target = 64u * (unsigned)(s + 1);
            while (true) {
                unsigned v;
                asm volatile("ld.global.acquire.gpu.u32 %0, [%1];" : "=r"(v) : "l"(&d_bar[dir]));
                if (v >= target) break;
                __nanosleep(64);
            }
            __threadfence();
        }
        __syncthreads();
    }
}

// ---------------------------------------------------------------------------
// kernel_launch
// ---------------------------------------------------------------------------
extern "C" void kernel_launch(void* const* d_in, const int* in_sizes, int n_in,
                              void* d_out, int out_size)
{
    const float* x    = (const float*)d_in[0];
    const int*   xlen = (const int*)  d_in[1];
    const float* am   = (const float*)d_in[2];
    const float* Wif  = (const float*)d_in[3];
    const float* Whf  = (const float*)d_in[4];
    const float* bif  = (const float*)d_in[5];
    const float* bhf  = (const float*)d_in[6];
    const float* Wib  = (const float*)d_in[7];
    const float* Whb  = (const float*)d_in[8];
    const float* bib  = (const float*)d_in[9];
    const float* bhb  = (const float*)d_in[10];
    float* out = (float*)d_out;

    void *pS, *pGf, *pGb, *pxhi, *pxlo, *pxThi, *pxTlo, *pShi, *pSlo,
         *pNXhi, *pNXlo, *pWhi, *pWlo;
    cudaGetSymbolAddress(&pS,    d_S);
    cudaGetSymbolAddress(&pGf,   d_Gf);
    cudaGetSymbolAddress(&pGb,   d_Gb);
    cudaGetSymbolAddress(&pxhi,  d_xhi);
    cudaGetSymbolAddress(&pxlo,  d_xlo);
    cudaGetSymbolAddress(&pxThi, d_xThi);
    cudaGetSymbolAddress(&pxTlo, d_xTlo);
    cudaGetSymbolAddress(&pShi,  d_Shi);
    cudaGetSymbolAddress(&pSlo,  d_Slo);
    cudaGetSymbolAddress(&pNXhi, d_NXhi);
    cudaGetSymbolAddress(&pNXlo, d_NXlo);
    cudaGetSymbolAddress(&pWhi,  d_Whi);
    cudaGetSymbolAddress(&pWlo,  d_Wlo);
    float* S = (float*)pS;
    float* Gf = (float*)pGf;
    float* Gb = (float*)pGb;
    __nv_bfloat16* xhi  = (__nv_bfloat16*)pxhi;
    __nv_bfloat16* xlo  = (__nv_bfloat16*)pxlo;
    __nv_bfloat16* xThi = (__nv_bfloat16*)pxThi;
    __nv_bfloat16* xTlo = (__nv_bfloat16*)pxTlo;
    __nv_bfloat16* Shi  = (__nv_bfloat16*)pShi;
    __nv_bfloat16* Slo  = (__nv_bfloat16*)pSlo;
    __nv_bfloat16* NXhi = (__nv_bfloat16*)pNXhi;
    __nv_bfloat16* NXlo = (__nv_bfloat16*)pNXlo;
    __nv_bfloat16* Whi0 = (__nv_bfloat16*)pWhi;
    __nv_bfloat16* Whi1 = Whi0 + (size_t)G4 * TWOH;
    __nv_bfloat16* Wlo0 = (__nv_bfloat16*)pWlo;
    __nv_bfloat16* Wlo1 = Wlo0 + (size_t)G4 * TWOH;

    cudaFuncSetAttribute(lstm_rec, cudaFuncAttributeMaxDynamicSharedMemorySize,
                         2 * 512 * 32 * (int)sizeof(float));
    cudaFuncSetAttribute(gemm_t3<0>, cudaFuncAttributeMaxDynamicSharedMemorySize, T3_DSMEM);
    cudaFuncSetAttribute(gemm_t3<1>, cudaFuncAttributeMaxDynamicSharedMemorySize, T3_DSMEM);
    cudaFuncSetAttribute(gemm_t3<2>, cudaFuncAttributeMaxDynamicSharedMemorySize, T3_DSMEM);

    init_state<<<256, 256>>>();

    // split x -> xhi/xlo + NX second half
    {
        size_t n4 = (size_t)BB * LL * HH / 4;
        split_x<<<(unsigned)((n4 + 255) / 256), 256>>>(x, xhi, xlo, NXhi, NXlo);
    }

    // x^T per batch for att@x B operand
    transpose_x<<<dim3(HH / 32, LL / 32, BB), dim3(32, 8)>>>(xhi, xlo, xThi, xTlo);

    // scores: S[b] = x_b * x_b^T  (tensor, K=1024)
    gemm_t3<0><<<dim3(LL / 128, LL / 128, BB), 256, T3_DSMEM>>>(
        xhi, xlo, xhi, xlo, HH, HH, HH,
        (size_t)LL * HH, (size_t)LL * HH,
        S, LL, (size_t)LL * LL, nullptr, nullptr, nullptr, nullptr);

    softmax512<<<dim3(LL, BB), 256>>>(S, am);

    // split attention probs
    {
        size_t n4 = (size_t)BB * LL * LL / 4;
        split_bf16<<<(unsigned)((n4 + 255) / 256), 256>>>(S, Shi, Slo, n4);
    }

    // att @ x -> NX[:, :, 0:1024] split-bf16 (tensor, K=512, B = x^T)
    gemm_t3<1><<<dim3(HH / 128, LL / 128, BB), 256, T3_DSMEM>>>(
        Shi, Slo, xThi, xTlo, LL, LL, LL,
        (size_t)LL * LL, (size_t)HH * LL,
        nullptr, 0, 0, NXhi, NXlo, nullptr, nullptr);

    // weight splits
    {
        size_t w4 = (size_t)G4 * TWOH / 4;
        split_bf16<<<(unsigned)((w4 + 255) / 256), 256>>>(Wif, Whi0, Wlo0, w4);
        split_bf16<<<(unsigned)((w4 + 255) / 256), 256>>>(Wib, Whi1, Wlo1, w4);
    }

    // gate precompute (tensor, K=2048), time-major out with bias
    gemm_t3<2><<<dim3(G4 / 128, (BB * LL) / 128, 1), 256, T3_DSMEM>>>(
        NXhi, NXlo, Whi0, Wlo0, TWOH, TWOH, TWOH, 0, 0,
        Gf, 0, 0, nullptr, nullptr, bif, bhf);
    gemm_t3<2><<<dim3(G4 / 128, (BB * LL) / 128, 1), 256, T3_DSMEM>>>(
        NXhi, NXlo, Whi1, Wlo1, TWOH, TWOH, TWOH, 0, 0,
        Gb, 0, 0, nullptr, nullptr, bib, bhb);

    // Persistent bidirectional recurrence
    lstm_rec<<<128, 256, 2 * 512 * 32 * sizeof(float)>>>(Whf, Whb, xlen, out);
}

// round 9
// speedup vs baseline: 2.6769x; 1.2990x over previous
#include <cuda_runtime.h>
#include <cuda_bf16.h>
#include <cstdint>
#include <cstddef>

// Problem constants
#define BB 32
#define LL 512
#define HH 1024
#define HID 512
#define G4 2048   // 4*HID
#define TWOH 2048 // 2*H

// ---------------------------------------------------------------------------
// Scratch (static __device__ arrays)
// ---------------------------------------------------------------------------
__device__ __align__(16) float d_S[(size_t)BB * LL * LL];
__device__ __align__(16) float d_Gf[(size_t)LL * BB * G4];
__device__ __align__(16) float d_Gb[(size_t)LL * BB * G4];
__device__ unsigned d_bar[2];
// h ping-pong in split bf16: [dir][buf][batch*512]
__device__ __align__(16) __nv_bfloat16 d_hbf_hi[2][2][BB * HID];
__device__ __align__(16) __nv_bfloat16 d_hbf_lo[2][2][BB * HID];
// bf16 split operands
__device__ __align__(16) __nv_bfloat16 d_xhi[(size_t)BB * LL * HH];
__device__ __align__(16) __nv_bfloat16 d_xlo[(size_t)BB * LL * HH];
__device__ __align__(16) __nv_bfloat16 d_xThi[(size_t)BB * HH * LL];
__device__ __align__(16) __nv_bfloat16 d_xTlo[(size_t)BB * HH * LL];
__device__ __align__(16) __nv_bfloat16 d_Shi[(size_t)BB * LL * LL];
__device__ __align__(16) __nv_bfloat16 d_Slo[(size_t)BB * LL * LL];
__device__ __align__(16) __nv_bfloat16 d_NXhi[(size_t)BB * LL * TWOH];
__device__ __align__(16) __nv_bfloat16 d_NXlo[(size_t)BB * LL * TWOH];
__device__ __align__(16) __nv_bfloat16 d_Whi[2][(size_t)G4 * TWOH];
__device__ __align__(16) __nv_bfloat16 d_Wlo[2][(size_t)G4 * TWOH];

// ---------------------------------------------------------------------------
// PTX helpers — base sm_100-safe (cp.async / ldmatrix / mma.sync)
// ---------------------------------------------------------------------------
__device__ __forceinline__ uint32_t smem_u32(const void* p) {
    uint32_t a;
    asm("{ .reg .u64 t; cvta.to.shared.u64 t, %1; cvt.u32.u64 %0, t; }" : "=r"(a) : "l"(p));
    return a;
}
__device__ __forceinline__ void cp_async16(uint32_t dst, const void* src) {
    asm volatile("cp.async.cg.shared.global [%0], [%1], 16;" :: "r"(dst), "l"(src));
}
#define CP_COMMIT() asm volatile("cp.async.commit_group;" ::: "memory")
#define CP_WAIT1()  asm volatile("cp.async.wait_group 1;" ::: "memory")
#define CP_WAIT0()  asm volatile("cp.async.wait_group 0;" ::: "memory")

__device__ __forceinline__ void ldm_x4(uint32_t* r, uint32_t a) {
    asm volatile("ldmatrix.sync.aligned.m8n8.x4.shared.b16 {%0,%1,%2,%3}, [%4];"
                 : "=r"(r[0]), "=r"(r[1]), "=r"(r[2]), "=r"(r[3]) : "r"(a));
}
__device__ __forceinline__ void mma_bf16(float* d, const uint32_t* a, const uint32_t* b) {
    asm volatile("mma.sync.aligned.m16n8k16.row.col.f32.bf16.bf16.f32 "
                 "{%0,%1,%2,%3}, {%4,%5,%6,%7}, {%8,%9}, {%0,%1,%2,%3};"
                 : "+f"(d[0]), "+f"(d[1]), "+f"(d[2]), "+f"(d[3])
                 : "r"(a[0]), "r"(a[1]), "r"(a[2]), "r"(a[3]), "r"(b[0]), "r"(b[1]));
}

#define SWZ128(off) ((off) ^ (((off) >> 3) & 0x70))

// ---------------------------------------------------------------------------
// init: zero split-h buffers + barrier counters
// ---------------------------------------------------------------------------
__global__ void init_state() {
    int i = blockIdx.x * blockDim.x + threadIdx.x;
    if (i < 2 * 2 * BB * HID) {
        ((__nv_bfloat16*)d_hbf_hi)[i] = __float2bfloat16(0.f);
        ((__nv_bfloat16*)d_hbf_lo)[i] = __float2bfloat16(0.f);
    }
    if (i < 2) d_bar[i] = 0u;
}

// ---------------------------------------------------------------------------
// Splits
// ---------------------------------------------------------------------------
__device__ __forceinline__ void split4(float4 v, __nv_bfloat162& H0, __nv_bfloat162& H1,
                                       __nv_bfloat162& L0, __nv_bfloat162& L1) {
    __nv_bfloat16 h0 = __float2bfloat16(v.x), h1 = __float2bfloat16(v.y);
    __nv_bfloat16 h2 = __float2bfloat16(v.z), h3 = __float2bfloat16(v.w);
    H0 = {h0, h1}; H1 = {h2, h3};
    L0 = {__float2bfloat16(v.x - __bfloat162float(h0)),
          __float2bfloat16(v.y - __bfloat162float(h1))};
    L1 = {__float2bfloat16(v.z - __bfloat162float(h2)),
          __float2bfloat16(v.w - __bfloat162float(h3))};
}

__global__ void __launch_bounds__(256) split_bf16(
    const float* __restrict__ src, __nv_bfloat16* __restrict__ hi,
    __nv_bfloat16* __restrict__ lo, size_t n4)
{
    size_t i = (size_t)blockIdx.x * 256 + threadIdx.x;
    if (i >= n4) return;
    __nv_bfloat162 H0, H1, L0, L1;
    split4(((const float4*)src)[i], H0, H1, L0, L1);
    ((__nv_bfloat162*)hi)[i * 2]     = H0;
    ((__nv_bfloat162*)hi)[i * 2 + 1] = H1;
    ((__nv_bfloat162*)lo)[i * 2]     = L0;
    ((__nv_bfloat162*)lo)[i * 2 + 1] = L1;
}

__global__ void __launch_bounds__(256) split_x(
    const float* __restrict__ x,
    __nv_bfloat16* __restrict__ xhi, __nv_bfloat16* __restrict__ xlo,
    __nv_bfloat16* __restrict__ NXhi, __nv_bfloat16* __restrict__ NXlo)
{
    size_t i = (size_t)blockIdx.x * 256 + threadIdx.x;
    if (i >= (size_t)BB * LL * HH / 4) return;
    __nv_bfloat162 H0, H1, L0, L1;
    split4(((const float4*)x)[i], H0, H1, L0, L1);
    ((__nv_bfloat162*)xhi)[i * 2]     = H0;
    ((__nv_bfloat162*)xhi)[i * 2 + 1] = H1;
    ((__nv_bfloat162*)xlo)[i * 2]     = L0;
    ((__nv_bfloat162*)xlo)[i * 2 + 1] = L1;
    size_t bl = i >> 8, d4 = i & 255;
    size_t o = bl * 1024 + 512 + d4 * 2;
    ((__nv_bfloat162*)NXhi)[o]     = H0;
    ((__nv_bfloat162*)NXhi)[o + 1] = H1;
    ((__nv_bfloat162*)NXlo)[o]     = L0;
    ((__nv_bfloat162*)NXlo)[o + 1] = L1;
}

__global__ void transpose_x(
    const __nv_bfloat16* __restrict__ hi, const __nv_bfloat16* __restrict__ lo,
    __nv_bfloat16* __restrict__ Thi, __nv_bfloat16* __restrict__ Tlo)
{
    __shared__ __nv_bfloat16 th[32][33], tl[32][33];
    const int b = blockIdx.z;
    const int d0 = blockIdx.x * 32, l0 = blockIdx.y * 32;
    const int tx = threadIdx.x, ty = threadIdx.y;
    const size_t si = (size_t)b * LL * HH;
    #pragma unroll
    for (int i = 0; i < 4; i++) {
        int l = ty + i * 8;
        th[l][tx] = hi[si + (size_t)(l0 + l) * HH + d0 + tx];
        tl[l][tx] = lo[si + (size_t)(l0 + l) * HH + d0 + tx];
    }
    __syncthreads();
    const size_t so = (size_t)b * HH * LL;
    #pragma unroll
    for (int i = 0; i < 4; i++) {
        int d = ty + i * 8;
        Thi[so + (size_t)(d0 + d) * LL + l0 + tx] = th[tx][d];
        Tlo[so + (size_t)(d0 + d) * LL + l0 + tx] = tl[tx][d];
    }
}

// ---------------------------------------------------------------------------
// Unified bf16-split tensor GEMM, 3-stage cp.async pipeline.
// ---------------------------------------------------------------------------
#define KC 64
#define TILEB 16384
#define STAGEB (4 * TILEB)
#define T3_DSMEM (1024 + 3 * STAGEB)

template <int EPI>
__global__ void __launch_bounds__(256) gemm_t3(
    const __nv_bfloat16* __restrict__ Ahi, const __nv_bfloat16* __restrict__ Alo,
    const __nv_bfloat16* __restrict__ Bhi, const __nv_bfloat16* __restrict__ Blo,
    int K, int lda, int ldb, size_t sA, size_t sB,
    float* __restrict__ Cf, int ldc, size_t sC,
    __nv_bfloat16* __restrict__ Chi, __nv_bfloat16* __restrict__ Clo,
    const float* __restrict__ bias1, const float* __restrict__ bias2)
{
    extern __shared__ char dsm[];
    char* basep = (char*)(((uintptr_t)dsm + 1023) & ~(uintptr_t)1023);
    const uint32_t sbase = smem_u32(basep);

    const int tid = threadIdx.x;
    const int wid = tid >> 5, lane = tid & 31;
    const int warp_m = wid >> 2, warp_n = wid & 3;
    const int m0 = blockIdx.y * 128, n0 = blockIdx.x * 128;
    const int z = blockIdx.z;
    Ahi += (size_t)z * sA; Alo += (size_t)z * sA;
    Bhi += (size_t)z * sB; Blo += (size_t)z * sB;

    float acc[4][4][4] = {};
    const int nchunk = K / KC;

    auto issue = [&](int chunk) {
        const uint32_t st = sbase + (chunk % 3) * STAGEB;
        const int kc = chunk * KC;
        #pragma unroll
        for (int i = 0; i < 4; i++) {
            int u = tid + i * 256;
            int r = u >> 3, cu = u & 7;
            uint32_t sw = SWZ128((uint32_t)(r * 128 + cu * 16));
            size_t ao = (size_t)(m0 + r) * lda + kc + cu * 8;
            size_t bo = (size_t)(n0 + r) * ldb + kc + cu * 8;
            cp_async16(st + sw,             Ahi + ao);
            cp_async16(st + TILEB + sw,     Alo + ao);
            cp_async16(st + 2 * TILEB + sw, Bhi + bo);
            cp_async16(st + 3 * TILEB + sw, Blo + bo);
        }
    };

    issue(0); CP_COMMIT();
    issue(1); CP_COMMIT();

    for (int c = 0; c < nchunk; c++) {
        CP_WAIT1();
        __syncthreads();
        if (c + 2 < nchunk) { issue(c + 2); CP_COMMIT(); }
        const uint32_t st = sbase + (c % 3) * STAGEB;

        #pragma unroll
        for (int ks = 0; ks < 4; ks++) {
            const int kb = ks * 32;
            uint32_t ah[4][4], al[4][4], bh[4][2], bl2[4][2];
            #pragma unroll
            for (int mt = 0; mt < 4; mt++) {
                int row = warp_m * 64 + mt * 16 + (lane & 15);
                uint32_t off = SWZ128((uint32_t)(row * 128 + kb + ((lane >> 4) * 16)));
                ldm_x4(ah[mt], st + off);
                ldm_x4(al[mt], st + TILEB + off);
            }
            #pragma unroll
            for (int ntp = 0; ntp < 2; ntp++) {
                int row = warp_n * 32 + ntp * 16 + ((lane >> 4) * 8) + (lane & 7);
                uint32_t off = SWZ128((uint32_t)(row * 128 + kb + (((lane >> 3) & 1) * 16)));
                uint32_t r4[4];
                ldm_x4(r4, st + 2 * TILEB + off);
                bh[2 * ntp][0] = r4[0]; bh[2 * ntp][1] = r4[1];
                bh[2 * ntp + 1][0] = r4[2]; bh[2 * ntp + 1][1] = r4[3];
                ldm_x4(r4, st + 3 * TILEB + off);
                bl2[2 * ntp][0] = r4[0]; bl2[2 * ntp][1] = r4[1];
                bl2[2 * ntp + 1][0] = r4[2]; bl2[2 * ntp + 1][1] = r4[3];
            }
            #pragma unroll
            for (int mt = 0; mt < 4; mt++)
                #pragma unroll
                for (int nt = 0; nt < 4; nt++) {
                    mma_bf16(acc[mt][nt], ah[mt], bh[nt]);
                    mma_bf16(acc[mt][nt], ah[mt], bl2[nt]);
                    mma_bf16(acc[mt][nt], al[mt], bh[nt]);
                }
        }
        __syncthreads();
    }

    // Epilogue
    const int g = lane >> 2, tc = lane & 3;
    #pragma unroll
    for (int nt = 0; nt < 4; nt++) {
        int col = n0 + warp_n * 32 + nt * 8 + tc * 2;
        float b0v = 0.f, b1v = 0.f;
        if (EPI == 2) {
            b0v = bias1[col] + bias2[col];
            b1v = bias1[col + 1] + bias2[col + 1];
        }
        #pragma unroll
        for (int mt = 0; mt < 4; mt++) {
            #pragma unroll
            for (int half = 0; half < 2; half++) {
                int ml = warp_m * 64 + mt * 16 + g + half * 8;
                float v0 = acc[mt][nt][half * 2] + b0v;
                float v1 = acc[mt][nt][half * 2 + 1] + b1v;
                if (EPI == 0) {
                    *(float2*)(Cf + (size_t)z * sC + (size_t)(m0 + ml) * ldc + col)
                        = make_float2(v0, v1);
                } else if (EPI == 1) {
                    size_t row = (size_t)z * LL + m0 + ml;
                    __nv_bfloat16 h0 = __float2bfloat16(v0), h1 = __float2bfloat16(v1);
                    __nv_bfloat162 hv = {h0, h1};
                    __nv_bfloat162 lv = {__float2bfloat16(v0 - __bfloat162float(h0)),
                                         __float2bfloat16(v1 - __bfloat162float(h1))};
                    *(__nv_bfloat162*)(Chi + row * TWOH + col) = hv;
                    *(__nv_bfloat162*)(Clo + row * TWOH + col) = lv;
                } else {
                    int m = m0 + ml;
                    int t = m & 511, b = m >> 9;
                    *(float2*)(Cf + ((size_t)t * 32 + b) * 2048 + col)
                        = make_float2(v0, v1);
                }
            }
        }
    }
}

// ---------------------------------------------------------------------------
// Masked softmax over last axis (512)
// ---------------------------------------------------------------------------
__global__ void __launch_bounds__(256) softmax512(float* __restrict__ S,
                                                  const float* __restrict__ mask)
{
    const int l = blockIdx.x, b = blockIdx.y;
    float* row = S + ((size_t)b * LL + l) * LL;
    const float* m = mask + (size_t)b * LL;
    const int tid = threadIdx.x;

    float m0 = m[tid], m1 = m[tid + 256];
    float v0 = (m0 > 0.5f) ? row[tid]       : -1e20f;
    float v1 = (m1 > 0.5f) ? row[tid + 256] : -1e20f;

    __shared__ float red[8];
    float mx = fmaxf(v0, v1);
    #pragma unroll
    for (int o = 16; o > 0; o >>= 1) mx = fmaxf(mx, __shfl_xor_sync(0xffffffffu, mx, o));
    if ((tid & 31) == 0) red[tid >> 5] = mx;
    __syncthreads();
    float bm = red[0];
    #pragma unroll
    for (int i = 1; i < 8; i++) bm = fmaxf(bm, red[i]);

    float e0 = expf(v0 - bm);
    float e1 = expf(v1 - bm);
    float sum = e0 + e1;
    #pragma unroll
    for (int o = 16; o > 0; o >>= 1) sum += __shfl_xor_sync(0xffffffffu, sum, o);
    __syncthreads();
    if ((tid & 31) == 0) red[tid >> 5] = sum;
    __syncthreads();
    float bs = 0.f;
    #pragma unroll
    for (int i = 0; i < 8; i++) bs += red[i];

    float inv = 1.0f / bs;
    row[tid]       = e0 * inv;
    row[tid + 256] = e1 * inv;
}

// ---------------------------------------------------------------------------
// Persistent bidirectional LSTM recurrence — TENSOR CORE version.
// ---------------------------------------------------------------------------
__device__ __forceinline__ float sigm(float x) { return 1.0f / (1.0f + expf(-x)); }

#define LWH 0
#define LWL 32768
#define LHH 65536
#define LHL 98304
#define LSTM_DSMEM 132096

__global__ void __launch_bounds__(256, 1) lstm_rec(
    const float* __restrict__ Whf, const float* __restrict__ Whb,
    const int* __restrict__ x_len, float* __restrict__ out)
{
    extern __shared__ char lsm[];
    char* basep = (char*)(((uintptr_t)lsm + 1023) & ~(uintptr_t)1023);
    const uint32_t sbase = smem_u32(basep);

    __shared__ float gbuf[32][33];
    __shared__ float sG[32][36];
    __shared__ float cbuf[8][32];
    __shared__ float hown[8][32];
    __shared__ int s_len[32];

    const int tid = threadIdx.x;
    const int wid = tid >> 5, lane = tid & 31;
    const int warp_m = wid >> 2, warp_n = wid & 3;
    const int dir = blockIdx.x >> 6;
    const int u0 = (blockIdx.x & 63) * 8;
    const float* __restrict__ G = dir ? d_Gb : d_Gf;
    const float* __restrict__ W = dir ? Whb : Whf;

    if (tid < 32) s_len[tid] = x_len[tid];
    {
        int ul = tid & 7, b = tid >> 3;
        cbuf[ul][b] = 0.f; hown[ul][b] = 0.f;
    }

    // Stage W_hh rows as bf16 hi/lo, chunked swizzled tiles
    {
        int lr = tid >> 3, kg = tid & 7;
        int r = (lr >> 3) * 512 + u0 + (lr & 7);
        const float4* wr = (const float4*)(W + (size_t)r * 512 + kg * 64);
        #pragma unroll
        for (int v = 0; v < 16; v++) {
            __nv_bfloat162 H0, H1, L0, L1;
            split4(wr[v], H0, H1, L0, L1);
            uint32_t off = kg * 4096 + SWZ128((uint32_t)(lr * 128 + v * 8));
            *(__nv_bfloat162*)(basep + LWH + off)     = H0;
            *(__nv_bfloat162*)(basep + LWH + off + 4) = H1;
            *(__nv_bfloat162*)(basep + LWL + off)     = L0;
            *(__nv_bfloat162*)(basep + LWL + off + 4) = L1;
        }
    }
    __syncthreads();

    const uint32_t aRowOff = (uint32_t)((warp_m * 16 + (lane & 15)) * 128 + (lane >> 4) * 16);
    const uint32_t bRowOff = (uint32_t)((warp_n * 8 + (lane & 7)) * 128 + ((lane >> 3) & 1) * 16);
    const uint32_t bTile = (lane < 16) ? (sbase + LWH) : (sbase + LWL);

    for (int s = 0; s < 512; s++) {
        const int t = dir ? (511 - s) : s;
        const int rb = s & 1, wb = rb ^ 1;
        const __nv_bfloat16* hgHi = &d_hbf_hi[dir][rb][0];
        const __nv_bfloat16* hgLo = &d_hbf_lo[dir][rb][0];

        #pragma unroll
        for (int i = 0; i < 8; i++) {
            int u = tid + i * 256;
            int b = u >> 6, ch = (u >> 3) & 7, cu = u & 7;
            uint32_t sw = ch * 4096 + SWZ128((uint32_t)(b * 128 + cu * 16));
            cp_async16(sbase + LHH + sw, hgHi + b * 512 + ch * 64 + cu * 8);
            cp_async16(sbase + LHL + sw, hgLo + b * 512 + ch * 64 + cu * 8);
        }
        CP_COMMIT();
        {
            int pair = tid >> 1, half = tid & 1;
            int b = pair >> 2, gate = pair & 3;
            const float* gsrc = G + ((size_t)t * 32 + b) * 2048 + gate * 512 + u0 + half * 4;
            cp_async16(smem_u32(&sG[b][gate * 8 + half * 4]), gsrc);
        }
        CP_COMMIT();
        CP_WAIT1();
        __syncthreads();

        float acc[4] = {0.f, 0.f, 0.f, 0.f};
        #pragma unroll 8
        for (int kst = 0; kst < 32; kst++) {
            uint32_t kc = (uint32_t)(kst >> 2) * 4096;
            uint32_t kb = (uint32_t)(kst & 3) * 32;
            uint32_t ao = kc + SWZ128(aRowOff + kb);
            uint32_t bo = kc + SWZ128(bRowOff + kb);
            uint32_t ah[4], al[4], bbx[4];
            ldm_x4(ah, sbase + LHH + ao);
            ldm_x4(al, sbase + LHL + ao);
            ldm_x4(bbx, bTile + bo);
            mma_bf16(acc, ah, bbx);
            mma_bf16(acc, ah, bbx + 2);
            mma_bf16(acc, al, bbx);
        }

        {
            int g = lane >> 2, tc = lane & 3;
            int n = warp_n * 8 + tc * 2, m = warp_m * 16 + g;
            gbuf[n][m]         = acc[0];
            gbuf[n + 1][m]     = acc[1];
            gbuf[n][m + 8]     = acc[2];
            gbuf[n + 1][m + 8] = acc[3];
        }
        CP_WAIT0();
        __syncthreads();

        {
            int b = tid >> 3, ul = tid & 7;
            float gi = gbuf[ul][b]      + sG[b][ul];
            float gf = gbuf[8 + ul][b]  + sG[b][8 + ul];
            float gg = gbuf[16 + ul][b] + sG[b][16 + ul];
            float go = gbuf[24 + ul][b] + sG[b][24 + ul];
            float c  = cbuf[ul][b];
            float nc = sigm(gf) * c + sigm(gi) * tanhf(gg);
            float nh = sigm(go) * tanhf(nc);
            bool valid = (t < s_len[b]);
            float hn = valid ? nh : hown[ul][b];
            float cn = valid ? nc : c;
            cbuf[ul][b] = cn;
            hown[ul][b] = hn;
            __nv_bfloat16 hhi = __float2bfloat16(hn);
            __nv_bfloat16 hlo = __float2bfloat16(hn - __bfloat162float(hhi));
            d_hbf_hi[dir][wb][b * 512 + u0 + ul] = hhi;
            d_hbf_lo[dir][wb][b * 512 + u0 + ul] = hlo;
            if (s == 511) out[(size_t)b * 1024 + dir * 512 + u0 + ul] = hn;
        }

        if (s == 511) break;

        __threadfence();
        __syncthreads();
        if (tid == 0) {
            atomicAdd(&d_bar[dir], 1u);
            const unsigned target = 64u * (unsigned)(s + 1);
            while (true) {
                unsigned v;
                asm volatile("ld.global.acquire.gpu.u32 %0, [%1];" : "=r"(v) : "l"(&d_bar[dir]));
                if (v >= target) break;
                __nanosleep(64);
            }
            __threadfence();
        }
        __syncthreads();
    }
}

// ---------------------------------------------------------------------------
// kernel_launch
// ---------------------------------------------------------------------------
extern "C" void kernel_launch(void* const* d_in, const int* in_sizes, int n_in,
                              void* d_out, int out_size)
{
    const float* x    = (const float*)d_in[0];
    const int*   xlen = (const int*)  d_in[1];
    const float* am   = (const float*)d_in[2];
    const float* Wif  = (const float*)d_in[3];
    const float* Whf  = (const float*)d_in[4];
    const float* bif  = (const float*)d_in[5];
    const float* bhf  = (const float*)d_in[6];
    const float* Wib  = (const float*)d_in[7];
    const float* Whb  = (const float*)d_in[8];
    const float* bib  = (const float*)d_in[9];
    const float* bhb  = (const float*)d_in[10];
    float* out = (float*)d_out;

    void *pS, *pGf, *pGb, *pxhi, *pxlo, *pxThi, *pxTlo, *pShi, *pSlo,
         *pNXhi, *pNXlo, *pWhi, *pWlo;
    cudaGetSymbolAddress(&pS,    d_S);
    cudaGetSymbolAddress(&pGf,   d_Gf);
    cudaGetSymbolAddress(&pGb,   d_Gb);
    cudaGetSymbolAddress(&pxhi,  d_xhi);
    cudaGetSymbolAddress(&pxlo,  d_xlo);
    cudaGetSymbolAddress(&pxThi, d_xThi);
    cudaGetSymbolAddress(&pxTlo, d_xTlo);
    cudaGetSymbolAddress(&pShi,  d_Shi);
    cudaGetSymbolAddress(&pSlo,  d_Slo);
    cudaGetSymbolAddress(&pNXhi, d_NXhi);
    cudaGetSymbolAddress(&pNXlo, d_NXlo);
    cudaGetSymbolAddress(&pWhi,  d_Whi);
    cudaGetSymbolAddress(&pWlo,  d_Wlo);
    float* S = (float*)pS;
    float* Gf = (float*)pGf;
    float* Gb = (float*)pGb;
    __nv_bfloat16* xhi  = (__nv_bfloat16*)pxhi;
    __nv_bfloat16* xlo  = (__nv_bfloat16*)pxlo;
    __nv_bfloat16* xThi = (__nv_bfloat16*)pxThi;
    __nv_bfloat16* xTlo = (__nv_bfloat16*)pxTlo;
    __nv_bfloat16* Shi  = (__nv_bfloat16*)pShi;
    __nv_bfloat16* Slo  = (__nv_bfloat16*)pSlo;
    __nv_bfloat16* NXhi = (__nv_bfloat16*)pNXhi;
    __nv_bfloat16* NXlo = (__nv_bfloat16*)pNXlo;
    __nv_bfloat16* Whi0 = (__nv_bfloat16*)pWhi;
    __nv_bfloat16* Whi1 = Whi0 + (size_t)G4 * TWOH;
    __nv_bfloat16* Wlo0 = (__nv_bfloat16*)pWlo;
    __nv_bfloat16* Wlo1 = Wlo0 + (size_t)G4 * TWOH;

    cudaFuncSetAttribute(lstm_rec, cudaFuncAttributeMaxDynamicSharedMemorySize, LSTM_DSMEM);
    cudaFuncSetAttribute(gemm_t3<0>, cudaFuncAttributeMaxDynamicSharedMemorySize, T3_DSMEM);
    cudaFuncSetAttribute(gemm_t3<1>, cudaFuncAttributeMaxDynamicSharedMemorySize, T3_DSMEM);
    cudaFuncSetAttribute(gemm_t3<2>, cudaFuncAttributeMaxDynamicSharedMemorySize, T3_DSMEM);

    init_state<<<256, 256>>>();

    {
        size_t n4 = (size_t)BB * LL * HH / 4;
        split_x<<<(unsigned)((n4 + 255) / 256), 256>>>(x, xhi, xlo, NXhi, NXlo);
    }

    transpose_x<<<dim3(HH / 32, LL / 32, BB), dim3(32, 8)>>>(xhi, xlo, xThi, xTlo);

    // scores
    gemm_t3<0><<<dim3(LL / 128, LL / 128, BB), 256, T3_DSMEM>>>(
        xhi, xlo, xhi, xlo, HH, HH, HH,
        (size_t)LL * HH, (size_t)LL * HH,
        S, LL, (size_t)LL * LL, nullptr, nullptr, nullptr, nullptr);

    softmax512<<<dim3(LL, BB), 256>>>(S, am);

    {
        size_t n4 = (size_t)BB * LL * LL / 4;
        split_bf16<<<(unsigned)((n4 + 255) / 256), 256>>>(S, Shi, Slo, n4);
    }

    // att @ x
    gemm_t3<1><<<dim3(HH / 128, LL / 128, BB), 256, T3_DSMEM>>>(
        Shi, Slo, xThi, xTlo, LL, LL, LL,
        (size_t)LL * LL, (size_t)HH * LL,
        nullptr, 0, 0, NXhi, NXlo, nullptr, nullptr);

    {
        size_t w4 = (size_t)G4 * TWOH / 4;
        split_bf16<<<(unsigned)((w4 + 255) / 256), 256>>>(Wif, Whi0, Wlo0, w4);
        split_bf16<<<(unsigned)((w4 + 255) / 256), 256>>>(Wib, Whi1, Wlo1, w4);
    }

    // gate precompute
    gemm_t3<2><<<dim3(G4 / 128, (BB * LL) / 128, 1), 256, T3_DSMEM>>>(
        NXhi, NXlo, Whi0, Wlo0, TWOH, TWOH, TWOH, 0, 0,
        Gf, 0, 0, nullptr, nullptr, bif, bhf);
    gemm_t3<2><<<dim3(G4 / 128, (BB * LL) / 128, 1), 256, T3_DSMEM>>>(
        NXhi, NXlo, Whi1, Wlo1, TWOH, TWOH, TWOH, 0, 0,
        Gb, 0, 0, nullptr, nullptr, bib, bhb);

    // Persistent bidirectional recurrence (tensor cores)
    lstm_rec<<<128, 256, LSTM_DSMEM>>>(Whf, Whb, xlen, out);
}